// round 3
// baseline (speedup 1.0000x reference)
#include <cuda_runtime.h>
#include <cuda_bf16.h>
#include <math.h>

#define Bsz   32
#define Mrows 65536
#define Wc    64
#define Kk    8
#define Rr    9
#define INF_  512
#define IFACE 138
#define NBLK  64          // distance blocks per batch
#define ROWS_PER_BLK (Mrows / NBLK)   // 1024
#define ULLMAX 0xFFFFFFFFFFFFFFFFull

// Output layout: gathered[:, :8, :] (32*8*64) | read_weights_new (32*1*9) | gathered (32*9*64)
#define OUT0_OFF 0
#define OUT1_OFF 16384
#define OUT2_OFF 16672

// ---------------- device scratch (no allocation allowed) ----------------
__device__ __align__(16) float g_q[Bsz * Wc];          // read_query per batch
__device__ __align__(16) float g_rv[Bsz * Rr * Wc];    // updated read vectors
__device__ float              g_drv[Bsz * Rr];         // ||rv - q||^2
__device__ int                g_flag[Mrows];           // scattered pos -> k (or -1)
__device__ unsigned long long g_cand[Bsz * NBLK * Kk]; // phase-A candidates

// ---------------- K0: init flag ----------------
__global__ void k_init_flag() {
    int i = blockIdx.x * blockDim.x + threadIdx.x;
    if (i < Mrows) g_flag[i] = -1;
}

// ---------------- K1: scatter table (last j wins, k = j%9) ----------------
__global__ void k_scatter(const int* __restrict__ read_positions) {
    __shared__ int s_pos[Bsz * Rr];
    int j = threadIdx.x;  // 288 threads
    if (j < Bsz * Rr) s_pos[j] = read_positions[j];
    __syncthreads();
    if (j < Bsz * Rr) {
        int p = s_pos[j];
        int maxj = j;
        for (int j2 = 0; j2 < Bsz * Rr; j2++)
            if (s_pos[j2] == p && j2 > maxj) maxj = j2;
        if (maxj == j) g_flag[p] = j % Rr;   // single writer per position
    }
}

// ---------------- K2: iface, ww, rv, d_rv per batch ----------------
__global__ __launch_bounds__(256) void k_iface(
    const float* __restrict__ xi, const float* __restrict__ W,
    const float* __restrict__ bias, const float* __restrict__ read_weights,
    const float* __restrict__ read_vectors)
{
    __shared__ float s_xi[INF_];
    __shared__ float s_if[IFACE];
    __shared__ float s_ww[Rr];
    __shared__ float s_rv[Rr * Wc];
    int b = blockIdx.x, t = threadIdx.x;

    for (int i = t; i < INF_; i += 256) s_xi[i] = xi[b * INF_ + i];
    __syncthreads();

    if (t < IFACE) {
        float acc = bias[t];
        #pragma unroll 4
        for (int i = 0; i < INF_; i++) acc = fmaf(s_xi[i], W[i * IFACE + t], acc);
        s_if[t] = acc;
    }
    __syncthreads();

    if (t < Wc) g_q[b * Wc + t] = s_if[t];
    if (t < Rr) {
        float gate = 1.0f / (1.0f + expf(-s_if[IFACE - 1]));
        float ig   = s_if[2 * Wc + t];
        float rw   = read_weights[b * Rr + t];
        s_ww[t] = gate * (ig * rw + (1.0f - ig));
    }
    __syncthreads();

    for (int i = t; i < Rr * Wc; i += 256) {
        int r = i >> 6, w = i & 63;
        float v = read_vectors[b * Rr * Wc + i] + s_ww[r] * s_if[Wc + w];
        s_rv[i] = v;
        g_rv[b * Rr * Wc + i] = v;
    }
    __syncthreads();

    if (t < Rr) {
        float acc = 0.0f;
        for (int w = 0; w < Wc; w++) {
            float d = s_rv[t * Wc + w] - s_if[w];
            acc = fmaf(d, d, acc);
        }
        g_drv[b * Rr + t] = acc;
    }
}

// ---------------- K3: streaming distance + per-block top-8 ----------------
__global__ __launch_bounds__(256) void k_dist(const float* __restrict__ sparse) {
    const int b    = blockIdx.y;
    const int t    = threadIdx.x;
    const int lane = t & 31, warp = t >> 5;
    const int l16  = lane & 15, sub = lane >> 4;
    const int rowInIter = warp * 2 + sub;            // 0..15
    const float* sp = sparse + (size_t)b * Mrows * Wc;

    float4 q4 = *(const float4*)(g_q + b * Wc + l16 * 4);

    unsigned long long best[Kk];
    #pragma unroll
    for (int i = 0; i < Kk; i++) best[i] = ULLMAX;

    const int row0 = blockIdx.x * ROWS_PER_BLK;
    const int iters = ROWS_PER_BLK / 16;             // 64

    #pragma unroll 1
    for (int it = 0; it < iters; it += 4) {
        float4 v[4]; int m[4];
        #pragma unroll
        for (int u = 0; u < 4; u++) {
            m[u] = row0 + (it + u) * 16 + rowInIter;
            v[u] = *(const float4*)(sp + (size_t)m[u] * Wc + l16 * 4);
        }
        #pragma unroll
        for (int u = 0; u < 4; u++) {
            float dx = v[u].x - q4.x, dy = v[u].y - q4.y;
            float dz = v[u].z - q4.z, dw = v[u].w - q4.w;
            float p = fmaf(dx, dx, fmaf(dy, dy, fmaf(dz, dz, dw * dw)));
            p += __shfl_xor_sync(0xffffffffu, p, 8, 16);
            p += __shfl_xor_sync(0xffffffffu, p, 4, 16);
            p += __shfl_xor_sync(0xffffffffu, p, 2, 16);
            p += __shfl_xor_sync(0xffffffffu, p, 1, 16);
            if (l16 == 0) {
                int f = g_flag[m[u]];
                if (f >= 0) p = g_drv[b * Rr + f];   // scattered row: true distance
                unsigned long long cand =
                    ((unsigned long long)__float_as_uint(p) << 32) | (unsigned)m[u];
                if (cand < best[7]) {
                    best[7] = cand;
                    #pragma unroll
                    for (int i = 7; i >= 1; i--) {
                        if (best[i] < best[i - 1]) {
                            unsigned long long tmp = best[i - 1];
                            best[i - 1] = best[i]; best[i] = tmp;
                        }
                    }
                }
            }
        }
    }

    // block merge: 16 leaders x 8 -> 128 candidates in shared, warp0 selects 8
    __shared__ unsigned long long s_c[16 * Kk];
    if (l16 == 0) {
        #pragma unroll
        for (int i = 0; i < Kk; i++) s_c[rowInIter * Kk + i] = best[i];
    }
    __syncthreads();

    if (warp == 0) {
        unsigned long long v0 = s_c[lane * 4 + 0], v1 = s_c[lane * 4 + 1];
        unsigned long long v2 = s_c[lane * 4 + 2], v3 = s_c[lane * 4 + 3];
        // sort 4 ascending (network)
        unsigned long long tmp;
        if (v1 < v0) { tmp = v0; v0 = v1; v1 = tmp; }
        if (v3 < v2) { tmp = v2; v2 = v3; v3 = tmp; }
        if (v2 < v0) { tmp = v0; v0 = v2; v2 = tmp; }
        if (v3 < v1) { tmp = v1; v1 = v3; v3 = tmp; }
        if (v2 < v1) { tmp = v1; v1 = v2; v2 = tmp; }

        unsigned long long* outc = g_cand + ((size_t)b * NBLK + blockIdx.x) * Kk;
        #pragma unroll 1
        for (int r = 0; r < Kk; r++) {
            unsigned long long myv = v0;
            unsigned long long g = myv;
            #pragma unroll
            for (int off = 16; off; off >>= 1) {
                unsigned long long o = __shfl_xor_sync(0xffffffffu, g, off);
                if (o < g) g = o;
            }
            if (g == myv) { v0 = v1; v1 = v2; v2 = v3; v3 = ULLMAX; }
            if (lane == 0) outc[r] = g;
        }
    }
}

// ---------------- K4: per-batch final merge + normalize + gather ----------------
__global__ __launch_bounds__(256) void k_final(
    const float* __restrict__ sparse, const int* __restrict__ last_used,
    float* __restrict__ out)
{
    int b = blockIdx.x, t = threadIdx.x, lane = t & 31;
    __shared__ unsigned long long s_sel[Kk];
    __shared__ int   s_pos[Rr];
    __shared__ float s_nd[Rr];

    if (t < 32) {
        const unsigned long long* cb = g_cand + (size_t)b * NBLK * Kk;
        unsigned long long best[Kk];
        #pragma unroll
        for (int i = 0; i < Kk; i++) best[i] = ULLMAX;
        #pragma unroll
        for (int i = 0; i < 16; i++) {
            unsigned long long cand = cb[lane * 16 + i];
            if (cand < best[7]) {
                best[7] = cand;
                #pragma unroll
                for (int j = 7; j >= 1; j--) {
                    if (best[j] < best[j - 1]) {
                        unsigned long long tmp = best[j - 1];
                        best[j - 1] = best[j]; best[j] = tmp;
                    }
                }
            }
        }
        #pragma unroll 1
        for (int r = 0; r < Kk; r++) {
            unsigned long long myv = best[0];
            unsigned long long g = myv;
            #pragma unroll
            for (int off = 16; off; off >>= 1) {
                unsigned long long o = __shfl_xor_sync(0xffffffffu, g, off);
                if (o < g) g = o;
            }
            if (g == myv) {
                #pragma unroll
                for (int j = 0; j < Kk - 1; j++) best[j] = best[j + 1];
                best[Kk - 1] = ULLMAX;
            }
            if (lane == 0) s_sel[r] = g;
        }
    }
    __syncthreads();

    if (t < Rr) {
        float d_t = (t < Kk) ? __uint_as_float((unsigned)(s_sel[t] >> 32)) : 0.0f;
        int   p_t = (t < Kk) ? (int)(unsigned)(s_sel[t] & 0xFFFFFFFFu) : last_used[b];
        float maxd = 0.0f;
        #pragma unroll
        for (int i = 0; i < Kk; i++) {
            float di = __uint_as_float((unsigned)(s_sel[i] >> 32));
            if (di > maxd) maxd = di;
        }
        s_pos[t] = p_t;
        s_nd[t]  = d_t / maxd;
    }
    __syncthreads();

    // read_weights_new
    if (t < Rr) out[OUT1_OFF + b * Rr + t] = s_nd[t];

    // gather 9 rows (flag-aware: scattered rows come from rv)
    for (int i = t; i < Rr * Wc; i += 256) {
        int k = i >> 6, w = i & 63;
        int m = s_pos[k];
        int f = g_flag[m];
        float val = (f >= 0) ? g_rv[b * Rr * Wc + f * Wc + w]
                             : sparse[((size_t)b * Mrows + m) * Wc + w];
        out[OUT2_OFF + b * Rr * Wc + i] = val;
        if (k < Kk) out[OUT0_OFF + b * Kk * Wc + k * Wc + w] = val;
    }
}

// ---------------- launch ----------------
extern "C" void kernel_launch(void* const* d_in, const int* in_sizes, int n_in,
                              void* d_out, int out_size) {
    const float* xi            = (const float*)d_in[0];
    const float* sparse        = (const float*)d_in[1];
    const float* read_weights  = (const float*)d_in[2];
    const float* read_vectors  = (const float*)d_in[3];
    const float* W             = (const float*)d_in[4];
    const float* bias          = (const float*)d_in[5];
    const int*   read_positions= (const int*)d_in[6];
    const int*   last_used     = (const int*)d_in[7];
    float* out = (float*)d_out;

    k_init_flag<<<Mrows / 1024, 1024>>>();
    k_scatter<<<1, Bsz * Rr>>>(read_positions);
    k_iface<<<Bsz, 256>>>(xi, W, bias, read_weights, read_vectors);
    k_dist<<<dim3(NBLK, Bsz), 256>>>(sparse);
    k_final<<<Bsz, 256>>>(sparse, last_used, out);
}

// round 6
// speedup vs baseline: 1.2360x; 1.2360x over previous
#include <cuda_runtime.h>
#include <cuda_bf16.h>
#include <math.h>

#define Bsz   32
#define Mrows 65536
#define Wc    64
#define Kk    8
#define Rr    9
#define INF_  512
#define IFACE 138
#define NBLK  64                       // distance blocks per batch
#define ROWS_PER_BLK (Mrows / NBLK)    // 1024
#define ULLMAX 0xFFFFFFFFFFFFFFFFull

// Output layout: gathered[:, :8, :] (32*8*64) | read_weights_new (32*1*9) | gathered (32*9*64)
#define OUT0_OFF 0
#define OUT1_OFF 16384
#define OUT2_OFF 16672

// ---------------- device scratch (no allocation allowed) ----------------
__device__ __align__(16) float g_q[Bsz * Wc];          // read_query per batch
__device__ __align__(16) float g_rv[Bsz * Rr * Wc];    // updated read vectors
__device__ float              g_drv[Bsz * Rr];         // ||rv - q||^2
__device__ int                g_flag[Mrows];           // scattered pos -> k (valid only where mask bit set)
__device__ unsigned           g_mask[Mrows / 32];      // transposed-per-1024-block bitmask (8 KB)
__device__ unsigned long long g_cand[Bsz * NBLK * Kk]; // phase-A candidates

// Transposed mask addressing: for row m,
//   blk = m>>10, rowInIter = m&15, itv = (m>>4)&63
//   word = blk*32 + rowInIter*2 + (itv>>5), bit = itv&31
// so a leader (fixed blk,rowInIter) owns 2 consecutive words = its 64 rows.

// ---------------- K1: zero mask + scatter table (last j wins, k = j%9) ----------------
__global__ __launch_bounds__(1024) void k_scatter(const int* __restrict__ read_positions) {
    __shared__ int s_pos[Bsz * Rr];
    int t = threadIdx.x;  // 1024 threads
    g_mask[t] = 0u;
    g_mask[t + 1024] = 0u;
    if (t < Bsz * Rr) s_pos[t] = read_positions[t];
    __syncthreads();
    if (t < Bsz * Rr) {
        int p = s_pos[t];
        bool win = true;
        for (int j2 = t + 1; j2 < Bsz * Rr; j2++)
            if (s_pos[j2] == p) { win = false; break; }
        if (win) {
            g_flag[p] = t % Rr;
            int blk = p >> 10, rIt = p & 15, itv = (p >> 4) & 63;
            atomicOr(&g_mask[blk * 32 + rIt * 2 + (itv >> 5)], 1u << (itv & 31));
        }
    }
}

// ---------------- K2: iface, ww, rv, d_rv per batch ----------------
__global__ __launch_bounds__(256) void k_iface(
    const float* __restrict__ xi, const float* __restrict__ W,
    const float* __restrict__ bias, const float* __restrict__ read_weights,
    const float* __restrict__ read_vectors)
{
    __shared__ float s_xi[INF_];
    __shared__ float s_if[IFACE];
    __shared__ float s_ww[Rr];
    __shared__ float s_rv[Rr * Wc];
    int b = blockIdx.x, t = threadIdx.x;

    for (int i = t; i < INF_; i += 256) s_xi[i] = xi[b * INF_ + i];
    __syncthreads();

    if (t < IFACE) {
        // 4 independent accumulator chains, 8-deep unroll -> MLP hides W load latency
        float a0 = 0.f, a1 = 0.f, a2 = 0.f, a3 = 0.f;
        #pragma unroll 2
        for (int i = 0; i < INF_; i += 8) {
            a0 = fmaf(s_xi[i + 0], W[(i + 0) * IFACE + t], a0);
            a1 = fmaf(s_xi[i + 1], W[(i + 1) * IFACE + t], a1);
            a2 = fmaf(s_xi[i + 2], W[(i + 2) * IFACE + t], a2);
            a3 = fmaf(s_xi[i + 3], W[(i + 3) * IFACE + t], a3);
            a0 = fmaf(s_xi[i + 4], W[(i + 4) * IFACE + t], a0);
            a1 = fmaf(s_xi[i + 5], W[(i + 5) * IFACE + t], a1);
            a2 = fmaf(s_xi[i + 6], W[(i + 6) * IFACE + t], a2);
            a3 = fmaf(s_xi[i + 7], W[(i + 7) * IFACE + t], a3);
        }
        s_if[t] = (a0 + a1) + (a2 + a3) + bias[t];
    }
    __syncthreads();

    if (t < Wc) g_q[b * Wc + t] = s_if[t];
    if (t < Rr) {
        float gate = 1.0f / (1.0f + expf(-s_if[IFACE - 1]));
        float ig   = s_if[2 * Wc + t];
        float rw   = read_weights[b * Rr + t];
        s_ww[t] = gate * (ig * rw + (1.0f - ig));
    }
    __syncthreads();

    for (int i = t; i < Rr * Wc; i += 256) {
        int r = i >> 6, w = i & 63;
        float v = read_vectors[b * Rr * Wc + i] + s_ww[r] * s_if[Wc + w];
        s_rv[i] = v;
        g_rv[b * Rr * Wc + i] = v;
    }
    __syncthreads();

    if (t < Rr) {
        float acc = 0.0f;
        for (int w = 0; w < Wc; w++) {
            float d = s_rv[t * Wc + w] - s_if[w];
            acc = fmaf(d, d, acc);
        }
        g_drv[b * Rr + t] = acc;
    }
}

// ---------------- K3: streaming distance + per-block top-8 ----------------
__global__ __launch_bounds__(256) void k_dist(const float* __restrict__ sparse) {
    const int b    = blockIdx.y;
    const int t    = threadIdx.x;
    const int lane = t & 31, warp = t >> 5;
    const int l16  = lane & 15, sub = lane >> 4;
    const int rowInIter = warp * 2 + sub;            // 0..15
    const int row0 = blockIdx.x * ROWS_PER_BLK;

    // streaming pointer: one float4 per lane, row stride = Wc/4 = 16 float4
    const float4* __restrict__ p =
        (const float4*)(sparse + ((size_t)b * Mrows + row0 + rowInIter) * Wc) + l16;

    float4 q4 = *(const float4*)(g_q + b * Wc + l16 * 4);

    // leader-owned 64-bit flag mask (covers all 64 rows this leader will see)
    unsigned mk0 = 0, mk1 = 0;
    bool anyflag = false;
    if (l16 == 0) {
        const unsigned* mw = g_mask + (blockIdx.x * 32 + rowInIter * 2);
        mk0 = mw[0]; mk1 = mw[1];
        anyflag = (mk0 | mk1) != 0u;
    }

    unsigned long long best[Kk];
    #pragma unroll
    for (int i = 0; i < Kk; i++) best[i] = ULLMAX;

    const int mbase = row0 + rowInIter;

    #pragma unroll 1
    for (int it = 0; it < 64; it += 4, p += 1024) {   // 4 iters * 16 rows * 16 f4
        float4 v[4];
        v[0] = __ldcs(p);
        v[1] = __ldcs(p + 256);
        v[2] = __ldcs(p + 512);
        v[3] = __ldcs(p + 768);
        #pragma unroll
        for (int u = 0; u < 4; u++) {
            float dx = v[u].x - q4.x, dy = v[u].y - q4.y;
            float dz = v[u].z - q4.z, dw = v[u].w - q4.w;
            float pd = fmaf(dx, dx, fmaf(dy, dy, fmaf(dz, dz, dw * dw)));
            pd += __shfl_xor_sync(0xffffffffu, pd, 8, 16);
            pd += __shfl_xor_sync(0xffffffffu, pd, 4, 16);
            pd += __shfl_xor_sync(0xffffffffu, pd, 2, 16);
            pd += __shfl_xor_sync(0xffffffffu, pd, 1, 16);
            if (l16 == 0) {
                int itv = it + u;
                int m = mbase + itv * 16;
                if (anyflag) {
                    unsigned w = (itv < 32) ? mk0 : mk1;
                    if ((w >> (itv & 31)) & 1u)
                        pd = g_drv[b * Rr + g_flag[m]];   // scattered row: true distance
                }
                unsigned long long cand =
                    ((unsigned long long)__float_as_uint(pd) << 32) | (unsigned)m;
                if (cand < best[7]) {
                    best[7] = cand;
                    #pragma unroll
                    for (int i = 7; i >= 1; i--) {
                        if (best[i] < best[i - 1]) {
                            unsigned long long tmp = best[i - 1];
                            best[i - 1] = best[i]; best[i] = tmp;
                        }
                    }
                }
            }
        }
    }

    // block merge: 16 leaders x 8 -> 128 candidates in shared, warp0 selects 8
    __shared__ unsigned long long s_c[16 * Kk];
    if (l16 == 0) {
        #pragma unroll
        for (int i = 0; i < Kk; i++) s_c[rowInIter * Kk + i] = best[i];
    }
    __syncthreads();

    if (warp == 0) {
        unsigned long long v0 = s_c[lane * 4 + 0], v1 = s_c[lane * 4 + 1];
        unsigned long long v2 = s_c[lane * 4 + 2], v3 = s_c[lane * 4 + 3];
        unsigned long long tmp;
        if (v1 < v0) { tmp = v0; v0 = v1; v1 = tmp; }
        if (v3 < v2) { tmp = v2; v2 = v3; v3 = tmp; }
        if (v2 < v0) { tmp = v0; v0 = v2; v2 = tmp; }
        if (v3 < v1) { tmp = v1; v1 = v3; v3 = tmp; }
        if (v2 < v1) { tmp = v1; v1 = v2; v2 = tmp; }

        unsigned long long* outc = g_cand + ((size_t)b * NBLK + blockIdx.x) * Kk;
        #pragma unroll 1
        for (int r = 0; r < Kk; r++) {
            unsigned long long myv = v0;
            unsigned long long g = myv;
            #pragma unroll
            for (int off = 16; off; off >>= 1) {
                unsigned long long o = __shfl_xor_sync(0xffffffffu, g, off);
                if (o < g) g = o;
            }
            if (g == myv) { v0 = v1; v1 = v2; v2 = v3; v3 = ULLMAX; }
            if (lane == 0) outc[r] = g;
        }
    }
}

// ---------------- K4: per-batch final merge + normalize + gather ----------------
__global__ __launch_bounds__(256) void k_final(
    const float* __restrict__ sparse, const int* __restrict__ last_used,
    float* __restrict__ out)
{
    int b = blockIdx.x, t = threadIdx.x, lane = t & 31;
    __shared__ unsigned long long s_sel[Kk];
    __shared__ int   s_pos[Rr];
    __shared__ float s_nd[Rr];

    if (t < 32) {
        const unsigned long long* cb = g_cand + (size_t)b * NBLK * Kk;
        unsigned long long best[Kk];
        #pragma unroll
        for (int i = 0; i < Kk; i++) best[i] = ULLMAX;
        #pragma unroll
        for (int i = 0; i < 16; i++) {
            unsigned long long cand = cb[lane * 16 + i];
            if (cand < best[7]) {
                best[7] = cand;
                #pragma unroll
                for (int j = 7; j >= 1; j--) {
                    if (best[j] < best[j - 1]) {
                        unsigned long long tmp = best[j - 1];
                        best[j - 1] = best[j]; best[j] = tmp;
                    }
                }
            }
        }
        #pragma unroll 1
        for (int r = 0; r < Kk; r++) {
            unsigned long long myv = best[0];
            unsigned long long g = myv;
            #pragma unroll
            for (int off = 16; off; off >>= 1) {
                unsigned long long o = __shfl_xor_sync(0xffffffffu, g, off);
                if (o < g) g = o;
            }
            if (g == myv) {
                #pragma unroll
                for (int j = 0; j < Kk - 1; j++) best[j] = best[j + 1];
                best[Kk - 1] = ULLMAX;
            }
            if (lane == 0) s_sel[r] = g;
        }
    }
    __syncthreads();

    if (t < Rr) {
        float d_t = (t < Kk) ? __uint_as_float((unsigned)(s_sel[t] >> 32)) : 0.0f;
        int   p_t = (t < Kk) ? (int)(unsigned)(s_sel[t] & 0xFFFFFFFFu) : last_used[b];
        float maxd = 0.0f;
        #pragma unroll
        for (int i = 0; i < Kk; i++) {
            float di = __uint_as_float((unsigned)(s_sel[i] >> 32));
            if (di > maxd) maxd = di;
        }
        s_pos[t] = p_t;
        s_nd[t]  = d_t / maxd;
    }
    __syncthreads();

    if (t < Rr) out[OUT1_OFF + b * Rr + t] = s_nd[t];

    // gather 9 rows (mask-aware: scattered rows come from rv)
    for (int i = t; i < Rr * Wc; i += 256) {
        int k = i >> 6, w = i & 63;
        int m = s_pos[k];
        int blk = m >> 10, rIt = m & 15, itv = (m >> 4) & 63;
        unsigned mw = g_mask[blk * 32 + rIt * 2 + (itv >> 5)];
        int f = ((mw >> (itv & 31)) & 1u) ? g_flag[m] : -1;
        float val = (f >= 0) ? g_rv[b * Rr * Wc + f * Wc + w]
                             : sparse[((size_t)b * Mrows + m) * Wc + w];
        out[OUT2_OFF + b * Rr * Wc + i] = val;
        if (k < Kk) out[OUT0_OFF + b * Kk * Wc + k * Wc + w] = val;
    }
}

// ---------------- launch ----------------
extern "C" void kernel_launch(void* const* d_in, const int* in_sizes, int n_in,
                              void* d_out, int out_size) {
    const float* xi            = (const float*)d_in[0];
    const float* sparse        = (const float*)d_in[1];
    const float* read_weights  = (const float*)d_in[2];
    const float* read_vectors  = (const float*)d_in[3];
    const float* W             = (const float*)d_in[4];
    const float* bias          = (const float*)d_in[5];
    const int*   read_positions= (const int*)d_in[6];
    const int*   last_used     = (const int*)d_in[7];
    float* out = (float*)d_out;

    k_scatter<<<1, 1024>>>(read_positions);
    k_iface<<<Bsz, 256>>>(xi, W, bias, read_weights, read_vectors);
    k_dist<<<dim3(NBLK, Bsz), 256>>>(sparse);
    k_final<<<Bsz, 256>>>(sparse, last_used, out);
}

// round 8
// speedup vs baseline: 1.2991x; 1.0511x over previous
#include <cuda_runtime.h>
#include <cuda_bf16.h>
#include <math.h>

#define Bsz   32
#define Mrows 65536
#define Wc    64
#define Kk    8
#define Rr    9
#define INF_  512
#define IFACE 138
#define NBLK  64                       // distance blocks per batch
#define ROWS_PER_BLK (Mrows / NBLK)    // 1024
#define ULLMAX 0xFFFFFFFFFFFFFFFFull

// Output layout: gathered[:, :8, :] (32*8*64) | read_weights_new (32*1*9) | gathered (32*9*64)
#define OUT0_OFF 0
#define OUT1_OFF 16384
#define OUT2_OFF 16672

// ---------------- device scratch (no allocation allowed) ----------------
__device__ __align__(16) float g_q[Bsz * Wc];          // read_query per batch
__device__ __align__(16) float g_rv[Bsz * Rr * Wc];    // updated read vectors
__device__ float              g_drv[Bsz * Rr];         // ||rv - q||^2
__device__ int                g_flag[Mrows];           // scattered pos -> k (valid only where mask bit set)
__device__ unsigned           g_mask[Mrows / 32];      // transposed-per-1024-block bitmask (8 KB)
__device__ unsigned long long g_cand[Bsz * NBLK * Kk]; // phase-A candidates
__device__ unsigned           g_cnt[Bsz];              // per-batch done counters (reset each replay)

// Transposed mask addressing: for row m,
//   blk = m>>10, rowInIter = m&15, itv = (m>>4)&63
//   word = blk*32 + rIt*2 + (itv>>5), bit = itv&31

// ---------------- K1: fused setup ----------------
// blocks 0..31 : iface/ww/rv/d_rv for batch b
// block 32     : zero mask + counters, build scatter table (last j wins, k = j%9)
__global__ __launch_bounds__(256) void k_setup(
    const float* __restrict__ xi, const float* __restrict__ W,
    const float* __restrict__ bias, const float* __restrict__ read_weights,
    const float* __restrict__ read_vectors, const int* __restrict__ read_positions)
{
    int b = blockIdx.x, t = threadIdx.x;

    if (b == Bsz) {
        __shared__ int s_pos[Bsz * Rr];
        #pragma unroll
        for (int i = 0; i < 8; i++) g_mask[t + i * 256] = 0u;
        if (t < Bsz) g_cnt[t] = 0u;
        for (int i = t; i < Bsz * Rr; i += 256) s_pos[i] = read_positions[i];
        __syncthreads();
        for (int j = t; j < Bsz * Rr; j += 256) {
            int p = s_pos[j];
            bool win = true;
            for (int j2 = j + 1; j2 < Bsz * Rr; j2++)
                if (s_pos[j2] == p) { win = false; break; }
            if (win) {
                g_flag[p] = j % Rr;
                int blk = p >> 10, rIt = p & 15, itv = (p >> 4) & 63;
                atomicOr(&g_mask[blk * 32 + rIt * 2 + (itv >> 5)], 1u << (itv & 31));
            }
        }
        return;
    }

    __shared__ float s_xi[INF_];
    __shared__ float s_if[IFACE];
    __shared__ float s_ww[Rr];
    __shared__ float s_rv[Rr * Wc];

    for (int i = t; i < INF_; i += 256) s_xi[i] = xi[b * INF_ + i];
    __syncthreads();

    if (t < IFACE) {
        float a0 = 0.f, a1 = 0.f, a2 = 0.f, a3 = 0.f;
        #pragma unroll 2
        for (int i = 0; i < INF_; i += 8) {
            a0 = fmaf(s_xi[i + 0], W[(i + 0) * IFACE + t], a0);
            a1 = fmaf(s_xi[i + 1], W[(i + 1) * IFACE + t], a1);
            a2 = fmaf(s_xi[i + 2], W[(i + 2) * IFACE + t], a2);
            a3 = fmaf(s_xi[i + 3], W[(i + 3) * IFACE + t], a3);
            a0 = fmaf(s_xi[i + 4], W[(i + 4) * IFACE + t], a0);
            a1 = fmaf(s_xi[i + 5], W[(i + 5) * IFACE + t], a1);
            a2 = fmaf(s_xi[i + 6], W[(i + 6) * IFACE + t], a2);
            a3 = fmaf(s_xi[i + 7], W[(i + 7) * IFACE + t], a3);
        }
        s_if[t] = (a0 + a1) + (a2 + a3) + bias[t];
    }
    __syncthreads();

    if (t < Wc) g_q[b * Wc + t] = s_if[t];
    if (t < Rr) {
        float gate = 1.0f / (1.0f + expf(-s_if[IFACE - 1]));
        float ig   = s_if[2 * Wc + t];
        float rw   = read_weights[b * Rr + t];
        s_ww[t] = gate * (ig * rw + (1.0f - ig));
    }
    __syncthreads();

    for (int i = t; i < Rr * Wc; i += 256) {
        int r = i >> 6, w = i & 63;
        float v = read_vectors[b * Rr * Wc + i] + s_ww[r] * s_if[Wc + w];
        s_rv[i] = v;
        g_rv[b * Rr * Wc + i] = v;
    }
    __syncthreads();

    if (t < Rr) {
        float acc = 0.0f;
        for (int w = 0; w < Wc; w++) {
            float d = s_rv[t * Wc + w] - s_if[w];
            acc = fmaf(d, d, acc);
        }
        g_drv[b * Rr + t] = acc;
    }
}

// ---------------- K2: streaming distance + per-block top-8 + fused per-batch finalize ----------------
__global__ __launch_bounds__(256) void k_dist(
    const float* __restrict__ sparse, const int* __restrict__ last_used,
    float* __restrict__ out)
{
    const int b    = blockIdx.y;
    const int t    = threadIdx.x;
    const int lane = t & 31, warp = t >> 5;
    const int l16  = lane & 15, sub = lane >> 4;
    const int rowInIter = warp * 2 + sub;            // 0..15
    const int row0 = blockIdx.x * ROWS_PER_BLK;

    // streaming pointer: one float4 per lane, row stride = Wc/4 = 16 float4
    const float4* __restrict__ p =
        (const float4*)(sparse + ((size_t)b * Mrows + row0 + rowInIter) * Wc) + l16;

    float4 q4 = *(const float4*)(g_q + b * Wc + l16 * 4);

    // leader-owned 64-bit flag mask (covers all 64 rows this leader will see)
    unsigned mk0 = 0, mk1 = 0;
    bool anyflag = false;
    if (l16 == 0) {
        const unsigned* mw = g_mask + (blockIdx.x * 32 + rowInIter * 2);
        mk0 = mw[0]; mk1 = mw[1];
        anyflag = (mk0 | mk1) != 0u;
    }

    unsigned long long best[Kk];
    #pragma unroll
    for (int i = 0; i < Kk; i++) best[i] = ULLMAX;

    const int mbase = row0 + rowInIter;

    #pragma unroll 1
    for (int it = 0; it < 64; it += 8, p += 2048) {   // 8 rows deep: MLP ~8
        float4 v[8];
        #pragma unroll
        for (int u = 0; u < 8; u++) v[u] = __ldcs(p + u * 256);
        #pragma unroll
        for (int u = 0; u < 8; u++) {
            float dx = v[u].x - q4.x, dy = v[u].y - q4.y;
            float dz = v[u].z - q4.z, dw = v[u].w - q4.w;
            float pd = fmaf(dx, dx, fmaf(dy, dy, fmaf(dz, dz, dw * dw)));
            pd += __shfl_xor_sync(0xffffffffu, pd, 8, 16);
            pd += __shfl_xor_sync(0xffffffffu, pd, 4, 16);
            pd += __shfl_xor_sync(0xffffffffu, pd, 2, 16);
            pd += __shfl_xor_sync(0xffffffffu, pd, 1, 16);
            if (l16 == 0) {
                int itv = it + u;
                int m = mbase + itv * 16;
                if (anyflag) {
                    unsigned w = (itv < 32) ? mk0 : mk1;
                    if ((w >> (itv & 31)) & 1u)
                        pd = g_drv[b * Rr + g_flag[m]];   // scattered row: true distance
                }
                unsigned long long cand =
                    ((unsigned long long)__float_as_uint(pd) << 32) | (unsigned)m;
                if (cand < best[7]) {
                    best[7] = cand;
                    #pragma unroll
                    for (int i = 7; i >= 1; i--) {
                        if (best[i] < best[i - 1]) {
                            unsigned long long tmp = best[i - 1];
                            best[i - 1] = best[i]; best[i] = tmp;
                        }
                    }
                }
            }
        }
    }

    // block merge: 16 leaders x 8 -> 128 candidates in shared, warp0 selects 8
    __shared__ unsigned long long s_c[16 * Kk];
    if (l16 == 0) {
        #pragma unroll
        for (int i = 0; i < Kk; i++) s_c[rowInIter * Kk + i] = best[i];
    }
    __syncthreads();

    if (warp == 0) {
        unsigned long long v0 = s_c[lane * 4 + 0], v1 = s_c[lane * 4 + 1];
        unsigned long long v2 = s_c[lane * 4 + 2], v3 = s_c[lane * 4 + 3];
        unsigned long long tmp;
        if (v1 < v0) { tmp = v0; v0 = v1; v1 = tmp; }
        if (v3 < v2) { tmp = v2; v2 = v3; v3 = tmp; }
        if (v2 < v0) { tmp = v0; v0 = v2; v2 = tmp; }
        if (v3 < v1) { tmp = v1; v1 = v3; v3 = tmp; }
        if (v2 < v1) { tmp = v1; v1 = v2; v2 = tmp; }

        unsigned long long* outc = g_cand + ((size_t)b * NBLK + blockIdx.x) * Kk;
        #pragma unroll 1
        for (int r = 0; r < Kk; r++) {
            unsigned long long myv = v0;
            unsigned long long g = myv;
            #pragma unroll
            for (int off = 16; off; off >>= 1) {
                unsigned long long o = __shfl_xor_sync(0xffffffffu, g, off);
                if (o < g) g = o;
            }
            if (g == myv) { v0 = v1; v1 = v2; v2 = v3; v3 = ULLMAX; }
            if (lane == 0) outc[r] = g;
        }
    }

    // ---- last-block-per-batch fused finalize (threadfence-reduction pattern) ----
    __shared__ int s_last;
    if (t == 0) {
        __threadfence();                       // publish this block's g_cand
        unsigned old = atomicAdd(&g_cnt[b], 1u);
        s_last = (old == NBLK - 1);
        __threadfence();                       // acquire other blocks' g_cand
    }
    __syncthreads();
    if (!s_last) return;

    __shared__ unsigned long long s_sel[Kk];
    __shared__ int   s_pos[Rr];
    __shared__ float s_nd[Rr];

    if (t < 32) {
        const unsigned long long* cb = g_cand + (size_t)b * NBLK * Kk;
        unsigned long long fb[Kk];
        #pragma unroll
        for (int i = 0; i < Kk; i++) fb[i] = ULLMAX;
        #pragma unroll
        for (int i = 0; i < 16; i++) {
            unsigned long long cand = cb[lane * 16 + i];
            if (cand < fb[7]) {
                fb[7] = cand;
                #pragma unroll
                for (int j = 7; j >= 1; j--) {
                    if (fb[j] < fb[j - 1]) {
                        unsigned long long tmp = fb[j - 1];
                        fb[j - 1] = fb[j]; fb[j] = tmp;
                    }
                }
            }
        }
        #pragma unroll 1
        for (int r = 0; r < Kk; r++) {
            unsigned long long myv = fb[0];
            unsigned long long g = myv;
            #pragma unroll
            for (int off = 16; off; off >>= 1) {
                unsigned long long o = __shfl_xor_sync(0xffffffffu, g, off);
                if (o < g) g = o;
            }
            if (g == myv) {
                #pragma unroll
                for (int j = 0; j < Kk - 1; j++) fb[j] = fb[j + 1];
                fb[Kk - 1] = ULLMAX;
            }
            if (lane == 0) s_sel[r] = g;
        }
    }
    __syncthreads();

    if (t < Rr) {
        float d_t = (t < Kk) ? __uint_as_float((unsigned)(s_sel[t] >> 32)) : 0.0f;
        int   p_t = (t < Kk) ? (int)(unsigned)(s_sel[t] & 0xFFFFFFFFu) : last_used[b];
        float maxd = 0.0f;
        #pragma unroll
        for (int i = 0; i < Kk; i++) {
            float di = __uint_as_float((unsigned)(s_sel[i] >> 32));
            if (di > maxd) maxd = di;
        }
        s_pos[t] = p_t;
        s_nd[t]  = d_t / maxd;
        out[OUT1_OFF + b * Rr + t] = s_nd[t];
    }
    __syncthreads();

    // gather 9 rows (mask-aware: scattered rows come from rv)
    for (int i = t; i < Rr * Wc; i += 256) {
        int k = i >> 6, w = i & 63;
        int m = s_pos[k];
        int blk = m >> 10, rIt = m & 15, itv = (m >> 4) & 63;
        unsigned mw = g_mask[blk * 32 + rIt * 2 + (itv >> 5)];
        int f = ((mw >> (itv & 31)) & 1u) ? g_flag[m] : -1;
        float val = (f >= 0) ? g_rv[b * Rr * Wc + f * Wc + w]
                             : sparse[((size_t)b * Mrows + m) * Wc + w];
        out[OUT2_OFF + b * Rr * Wc + i] = val;
        if (k < Kk) out[OUT0_OFF + b * Kk * Wc + k * Wc + w] = val;
    }
}

// ---------------- launch ----------------
extern "C" void kernel_launch(void* const* d_in, const int* in_sizes, int n_in,
                              void* d_out, int out_size) {
    const float* xi            = (const float*)d_in[0];
    const float* sparse        = (const float*)d_in[1];
    const float* read_weights  = (const float*)d_in[2];
    const float* read_vectors  = (const float*)d_in[3];
    const float* W             = (const float*)d_in[4];
    const float* bias          = (const float*)d_in[5];
    const int*   read_positions= (const int*)d_in[6];
    const int*   last_used     = (const int*)d_in[7];
    float* out = (float*)d_out;

    k_setup<<<Bsz + 1, 256>>>(xi, W, bias, read_weights, read_vectors, read_positions);
    k_dist<<<dim3(NBLK, Bsz), 256>>>(sparse, last_used, out);
}

// round 9
// speedup vs baseline: 1.7068x; 1.3138x over previous
#include <cuda_runtime.h>
#include <cuda_bf16.h>
#include <math.h>

#define Bsz   32
#define Mrows 65536
#define Wc    64
#define Kk    8
#define Rr    9
#define INF_  512
#define IFACE 138
#define NBLK  64                       // distance blocks per batch
#define ROWS_PER_BLK (Mrows / NBLK)    // 1024
#define ULLMAX 0xFFFFFFFFFFFFFFFFull

// Output layout: gathered[:, :8, :] (32*8*64) | read_weights_new (32*1*9) | gathered (32*9*64)
#define OUT0_OFF 0
#define OUT1_OFF 16384
#define OUT2_OFF 16672

typedef unsigned long long u64;

// ---------------- device scratch (no allocation allowed) ----------------
__device__ __align__(16) float g_q[Bsz * Wc];          // read_query per batch
__device__ __align__(16) float g_rv[Bsz * Rr * Wc];    // updated read vectors
__device__ float              g_drv[Bsz * Rr];         // ||rv - q||^2
__device__ int                g_flag[Mrows];           // scattered pos -> k (valid only where mask bit set)
__device__ unsigned           g_mask[Mrows / 32];      // per-(block,leader) bitmask (8 KB)
__device__ u64                g_cand[Bsz * NBLK * Kk]; // phase-A candidates
__device__ unsigned           g_cnt[Bsz];              // per-batch done counters (reset each replay)

// Mask addressing: for row m,  word = (m>>10)*32 + (m&31),  bit = (m>>5)&31.
// A leader (block blk, slot L = m&31) owns exactly one word = its 32 rows.

// ---------------- packed f32x2 helpers (PTX-only; ptxas won't auto-fuse) ----------------
__device__ __forceinline__ u64 pack2(float lo, float hi) {
    u64 r; asm("mov.b64 %0,{%1,%2};" : "=l"(r) : "f"(lo), "f"(hi)); return r;
}
__device__ __forceinline__ void unpack2(u64 v, float& lo, float& hi) {
    asm("mov.b64 {%0,%1},%2;" : "=f"(lo), "=f"(hi) : "l"(v));
}
__device__ __forceinline__ u64 addx2(u64 a, u64 b) {
    u64 r; asm("add.rn.f32x2 %0,%1,%2;" : "=l"(r) : "l"(a), "l"(b)); return r;
}
__device__ __forceinline__ u64 mulx2(u64 a, u64 b) {
    u64 r; asm("mul.rn.f32x2 %0,%1,%2;" : "=l"(r) : "l"(a), "l"(b)); return r;
}
__device__ __forceinline__ u64 fmax2(u64 a, u64 b, u64 c) {
    u64 r; asm("fma.rn.f32x2 %0,%1,%2,%3;" : "=l"(r) : "l"(a), "l"(b), "l"(c)); return r;
}

// ---------------- K1: fused setup ----------------
// blocks 0..31 : iface/ww/rv/d_rv for batch b
// block 32     : zero mask + counters, build scatter table (last j wins, k = j%9)
__global__ __launch_bounds__(256) void k_setup(
    const float* __restrict__ xi, const float* __restrict__ W,
    const float* __restrict__ bias, const float* __restrict__ read_weights,
    const float* __restrict__ read_vectors, const int* __restrict__ read_positions)
{
    int b = blockIdx.x, t = threadIdx.x;

    if (b == Bsz) {
        __shared__ int s_pos[Bsz * Rr];
        #pragma unroll
        for (int i = 0; i < 8; i++) g_mask[t + i * 256] = 0u;
        if (t < Bsz) g_cnt[t] = 0u;
        for (int i = t; i < Bsz * Rr; i += 256) s_pos[i] = read_positions[i];
        __syncthreads();
        for (int j = t; j < Bsz * Rr; j += 256) {
            int p = s_pos[j];
            bool win = true;
            for (int j2 = j + 1; j2 < Bsz * Rr; j2++)
                if (s_pos[j2] == p) { win = false; break; }
            if (win) {
                g_flag[p] = j % Rr;
                atomicOr(&g_mask[(p >> 10) * 32 + (p & 31)], 1u << ((p >> 5) & 31));
            }
        }
        return;
    }

    __shared__ float s_xi[INF_];
    __shared__ float s_if[IFACE];
    __shared__ float s_ww[Rr];
    __shared__ float s_rv[Rr * Wc];

    for (int i = t; i < INF_; i += 256) s_xi[i] = xi[b * INF_ + i];
    __syncthreads();

    if (t < IFACE) {
        float a0 = 0.f, a1 = 0.f, a2 = 0.f, a3 = 0.f;
        #pragma unroll 2
        for (int i = 0; i < INF_; i += 8) {
            a0 = fmaf(s_xi[i + 0], W[(i + 0) * IFACE + t], a0);
            a1 = fmaf(s_xi[i + 1], W[(i + 1) * IFACE + t], a1);
            a2 = fmaf(s_xi[i + 2], W[(i + 2) * IFACE + t], a2);
            a3 = fmaf(s_xi[i + 3], W[(i + 3) * IFACE + t], a3);
            a0 = fmaf(s_xi[i + 4], W[(i + 4) * IFACE + t], a0);
            a1 = fmaf(s_xi[i + 5], W[(i + 5) * IFACE + t], a1);
            a2 = fmaf(s_xi[i + 6], W[(i + 6) * IFACE + t], a2);
            a3 = fmaf(s_xi[i + 7], W[(i + 7) * IFACE + t], a3);
        }
        s_if[t] = (a0 + a1) + (a2 + a3) + bias[t];
    }
    __syncthreads();

    if (t < Wc) g_q[b * Wc + t] = s_if[t];
    if (t < Rr) {
        float gate = 1.0f / (1.0f + expf(-s_if[IFACE - 1]));
        float ig   = s_if[2 * Wc + t];
        float rw   = read_weights[b * Rr + t];
        s_ww[t] = gate * (ig * rw + (1.0f - ig));
    }
    __syncthreads();

    for (int i = t; i < Rr * Wc; i += 256) {
        int r = i >> 6, w = i & 63;
        float v = read_vectors[b * Rr * Wc + i] + s_ww[r] * s_if[Wc + w];
        s_rv[i] = v;
        g_rv[b * Rr * Wc + i] = v;
    }
    __syncthreads();

    if (t < Rr) {
        float acc = 0.0f;
        for (int w = 0; w < Wc; w++) {
            float d = s_rv[t * Wc + w] - s_if[w];
            acc = fmaf(d, d, acc);
        }
        g_drv[b * Rr + t] = acc;
    }
}

// ---------------- distance for one row (8 lanes x 32B), packed f32x2 ----------------
__device__ __forceinline__ float row_dist(longlong2 r0, longlong2 r1,
                                          u64 nq0, u64 nq1, u64 nq2, u64 nq3) {
    u64 d0 = addx2((u64)r0.x, nq0);
    u64 d1 = addx2((u64)r0.y, nq1);
    u64 d2 = addx2((u64)r1.x, nq2);
    u64 d3 = addx2((u64)r1.y, nq3);
    u64 acc = mulx2(d0, d0);
    acc = fmax2(d1, d1, acc);
    acc = fmax2(d2, d2, acc);
    acc = fmax2(d3, d3, acc);
    float lo, hi; unpack2(acc, lo, hi);
    float s = lo + hi;
    s += __shfl_xor_sync(0xffffffffu, s, 4, 8);
    s += __shfl_xor_sync(0xffffffffu, s, 2, 8);
    s += __shfl_xor_sync(0xffffffffu, s, 1, 8);
    return s;
}

__device__ __forceinline__ void insert_cand(u64* best, u64 cand) {
    if (cand < best[7]) {
        best[7] = cand;
        #pragma unroll
        for (int i = 7; i >= 1; i--) {
            if (best[i] < best[i - 1]) {
                u64 tmp = best[i - 1]; best[i - 1] = best[i]; best[i] = tmp;
            }
        }
    }
}

// ---------------- K2: streaming distance + per-block top-8 + fused finalize ----------------
__global__ __launch_bounds__(256) void k_dist(
    const float* __restrict__ sparse, const int* __restrict__ last_used,
    float* __restrict__ out)
{
    const int b    = blockIdx.y;
    const int t    = threadIdx.x;
    const int lane = t & 31, warp = t >> 5;
    const int lir  = lane & 7;                 // lane-in-row (8 lanes x 32B = 256B row)
    const int L    = warp * 4 + (lane >> 3);   // leader slot 0..31
    const int row0 = blockIdx.x * ROWS_PER_BLK;

    // per-pass: 32 rows (block covers 8 warps x 4 rows); 32 passes of stride 32
    const longlong2* __restrict__ p =
        (const longlong2*)(sparse + ((size_t)b * Mrows + row0 + L) * Wc) + lir * 2;

    const float4* qp = (const float4*)(g_q + b * Wc + lir * 8);
    float4 qa = qp[0], qb = qp[1];
    u64 nq0 = pack2(-qa.x, -qa.y), nq1 = pack2(-qa.z, -qa.w);
    u64 nq2 = pack2(-qb.x, -qb.y), nq3 = pack2(-qb.z, -qb.w);

    unsigned mk = 0;
    bool anyflag = false;
    if (lir == 0) {
        mk = g_mask[blockIdx.x * 32 + L];
        anyflag = (mk != 0u);
    }

    u64 best[Kk];
    #pragma unroll
    for (int i = 0; i < Kk; i++) best[i] = ULLMAX;

    const int mbase = row0 + L;

    #pragma unroll 1
    for (int pass = 0; pass < 32; pass += 2, p += 1024) {   // 1024 ll2 = 2 passes * 32 rows * 16 ll2... (512/pass)
        longlong2 a0 = __ldcs(p);
        longlong2 a1 = __ldcs(p + 1);
        longlong2 c0 = __ldcs(p + 512);
        longlong2 c1 = __ldcs(p + 513);

        float s0 = row_dist(a0, a1, nq0, nq1, nq2, nq3);
        float s1 = row_dist(c0, c1, nq0, nq1, nq2, nq3);

        if (lir == 0) {
            int m0 = mbase + (pass << 5);
            int m1 = m0 + 32;
            if (anyflag) {
                if ((mk >> pass) & 1u)       s0 = g_drv[b * Rr + g_flag[m0]];
                if ((mk >> (pass + 1)) & 1u) s1 = g_drv[b * Rr + g_flag[m1]];
            }
            insert_cand(best, ((u64)__float_as_uint(s0) << 32) | (unsigned)m0);
            insert_cand(best, ((u64)__float_as_uint(s1) << 32) | (unsigned)m1);
        }
    }

    // block merge: 32 leaders x 8 sorted -> shared, warp0 extracts global top-8
    __shared__ u64 s_c[32 * Kk];
    if (lir == 0) {
        #pragma unroll
        for (int i = 0; i < Kk; i++) s_c[L * Kk + i] = best[i];
    }
    __syncthreads();

    if (warp == 0) {
        u64 v[Kk];
        #pragma unroll
        for (int i = 0; i < Kk; i++) v[i] = s_c[lane * Kk + i];   // lane <-> leader, sorted asc

        u64* outc = g_cand + ((size_t)b * NBLK + blockIdx.x) * Kk;
        #pragma unroll 1
        for (int r = 0; r < Kk; r++) {
            u64 my = v[0];
            u64 g = my;
            #pragma unroll
            for (int off = 16; off; off >>= 1) {
                u64 o = __shfl_xor_sync(0xffffffffu, g, off);
                if (o < g) g = o;
            }
            if (g == my) {
                #pragma unroll
                for (int i = 0; i < Kk - 1; i++) v[i] = v[i + 1];
                v[Kk - 1] = ULLMAX;
            }
            if (lane == 0) outc[r] = g;
        }
    }

    // ---- last-block-per-batch fused finalize (threadfence-reduction pattern) ----
    __shared__ int s_last;
    if (t == 0) {
        __threadfence();                       // publish this block's g_cand
        unsigned old = atomicAdd(&g_cnt[b], 1u);
        s_last = (old == NBLK - 1);
        __threadfence();                       // acquire other blocks' g_cand
    }
    __syncthreads();
    if (!s_last) return;

    __shared__ u64   s_sel[Kk];
    __shared__ int   s_pos[Rr];
    __shared__ float s_nd[Rr];

    if (t < 32) {
        const u64* cb = g_cand + (size_t)b * NBLK * Kk;
        u64 fb[Kk];
        #pragma unroll
        for (int i = 0; i < Kk; i++) fb[i] = ULLMAX;
        #pragma unroll
        for (int i = 0; i < 16; i++) insert_cand(fb, cb[lane * 16 + i]);
        #pragma unroll 1
        for (int r = 0; r < Kk; r++) {
            u64 my = fb[0];
            u64 g = my;
            #pragma unroll
            for (int off = 16; off; off >>= 1) {
                u64 o = __shfl_xor_sync(0xffffffffu, g, off);
                if (o < g) g = o;
            }
            if (g == my) {
                #pragma unroll
                for (int j = 0; j < Kk - 1; j++) fb[j] = fb[j + 1];
                fb[Kk - 1] = ULLMAX;
            }
            if (lane == 0) s_sel[r] = g;
        }
    }
    __syncthreads();

    if (t < Rr) {
        float d_t = (t < Kk) ? __uint_as_float((unsigned)(s_sel[t] >> 32)) : 0.0f;
        int   p_t = (t < Kk) ? (int)(unsigned)(s_sel[t] & 0xFFFFFFFFu) : last_used[b];
        float maxd = 0.0f;
        #pragma unroll
        for (int i = 0; i < Kk; i++) {
            float di = __uint_as_float((unsigned)(s_sel[i] >> 32));
            if (di > maxd) maxd = di;
        }
        s_pos[t] = p_t;
        s_nd[t]  = d_t / maxd;
        out[OUT1_OFF + b * Rr + t] = s_nd[t];
    }
    __syncthreads();

    // gather 9 rows (mask-aware: scattered rows come from rv)
    for (int i = t; i < Rr * Wc; i += 256) {
        int k = i >> 6, w = i & 63;
        int m = s_pos[k];
        unsigned mw = g_mask[(m >> 10) * 32 + (m & 31)];
        int f = ((mw >> ((m >> 5) & 31)) & 1u) ? g_flag[m] : -1;
        float val = (f >= 0) ? g_rv[b * Rr * Wc + f * Wc + w]
                             : sparse[((size_t)b * Mrows + m) * Wc + w];
        out[OUT2_OFF + b * Rr * Wc + i] = val;
        if (k < Kk) out[OUT0_OFF + b * Kk * Wc + k * Wc + w] = val;
    }
}

// ---------------- launch ----------------
extern "C" void kernel_launch(void* const* d_in, const int* in_sizes, int n_in,
                              void* d_out, int out_size) {
    const float* xi            = (const float*)d_in[0];
    const float* sparse        = (const float*)d_in[1];
    const float* read_weights  = (const float*)d_in[2];
    const float* read_vectors  = (const float*)d_in[3];
    const float* W             = (const float*)d_in[4];
    const float* bias          = (const float*)d_in[5];
    const int*   read_positions= (const int*)d_in[6];
    const int*   last_used     = (const int*)d_in[7];
    float* out = (float*)d_out;

    k_setup<<<Bsz + 1, 256>>>(xi, W, bias, read_weights, read_vectors, read_positions);
    k_dist<<<dim3(NBLK, Bsz), 256>>>(sparse, last_used, out);
}